// round 1
// baseline (speedup 1.0000x reference)
#include <cuda_runtime.h>
#include <cuda_bf16.h>
#include <cstdint>
#include <math.h>

// ---------------- problem constants ----------------
#define BATCH   32
#define SEQ     512
#define NTOK    (BATCH*SEQ)      // 16384
#define HID     768
#define FFD     3072
#define NHEADS  12
#define DHEAD   64
#define NLAYER  12
#define NSPAN   256
#define NLBL    9

// ---------------- scratch (device globals: allocation-free) ----------------
__device__ float g_h  [NTOK*HID];
__device__ float g_h2 [NTOK*HID];
__device__ float g_q  [NTOK*HID];
__device__ float g_k  [NTOK*HID];
__device__ float g_v  [NTOK*HID];
__device__ float g_ctx[NTOK*HID];
__device__ float g_tmp[NTOK*HID];
__device__ float g_ff [NTOK*FFD];
__device__ float g_sc [(size_t)BATCH*NHEADS*SEQ*SEQ];   // 402 MB

// ---------------- small helpers ----------------
__device__ __forceinline__ uint32_t f2tf32(float x) {
    uint32_t r;
    asm("cvt.rna.tf32.f32 %0, %1;\n" : "=r"(r) : "f"(x));
    return r;
}

__device__ __forceinline__ void mma8(float* d, const uint32_t* a, const uint32_t* b) {
    asm volatile(
        "mma.sync.aligned.m16n8k8.row.col.f32.tf32.tf32.f32 "
        "{%0,%1,%2,%3}, {%4,%5,%6,%7}, {%8,%9}, {%0,%1,%2,%3};\n"
        : "+f"(d[0]), "+f"(d[1]), "+f"(d[2]), "+f"(d[3])
        : "r"(a[0]), "r"(a[1]), "r"(a[2]), "r"(a[3]), "r"(b[0]), "r"(b[1]));
}

__device__ __forceinline__ void cp16(void* dst, const void* src, bool valid) {
    uint32_t d = (uint32_t)__cvta_generic_to_shared(dst);
    int sz = valid ? 16 : 0;
    asm volatile("cp.async.cg.shared.global [%0], [%1], 16, %2;\n"
                 :: "r"(d), "l"(src), "r"(sz));
}
__device__ __forceinline__ void cp_commit() { asm volatile("cp.async.commit_group;\n"); }
template<int N> __device__ __forceinline__ void cp_wait() {
    asm volatile("cp.async.wait_group %0;\n" :: "n"(N));
}

__device__ __forceinline__ float gelu_f(float x) {
    return 0.5f * x * (1.0f + erff(x * 0.7071067811865476f));
}

template<int NWARP>
__device__ __forceinline__ float blk_sum(float v, float* sh, int tid) {
    #pragma unroll
    for (int o = 16; o > 0; o >>= 1) v += __shfl_xor_sync(0xffffffffu, v, o);
    if ((tid & 31) == 0) sh[tid >> 5] = v;
    __syncthreads();
    float t = (tid < NWARP) ? sh[tid] : 0.0f;
    #pragma unroll
    for (int o = NWARP >> 1; o > 0; o >>= 1) t += __shfl_xor_sync(0xffffffffu, t, o);
    if (tid == 0) sh[0] = t;
    __syncthreads();
    float r = sh[0];
    __syncthreads();
    return r;
}

template<int NWARP>
__device__ __forceinline__ float blk_max(float v, float* sh, int tid) {
    #pragma unroll
    for (int o = 16; o > 0; o >>= 1) v = fmaxf(v, __shfl_xor_sync(0xffffffffu, v, o));
    if ((tid & 31) == 0) sh[tid >> 5] = v;
    __syncthreads();
    float t = (tid < NWARP) ? sh[tid] : -3.4e38f;
    #pragma unroll
    for (int o = NWARP >> 1; o > 0; o >>= 1) t = fmaxf(t, __shfl_xor_sync(0xffffffffu, t, o));
    if (tid == 0) sh[0] = t;
    __syncthreads();
    float r = sh[0];
    __syncthreads();
    return r;
}

// ---------------- generic TF32 GEMM ----------------
// C[M,N] = alpha * A[M,K] @ (TRANS_B ? B[N,K]^T : B[K,N]) + bias[N], EPI: 0 none, 1 GELU
// Batched via blockIdx.z: offset = (z/innerN)*s?o + (z%innerN)*s?i
#define BM 128
#define BN 128
#define BKT 16
#define AST 20     // BK + 4 pad
#define BNN 136    // BN + 8 pad
#define BNT 20     // BK + 4 pad

template<bool TRANS_B, int EPI>
__global__ __launch_bounds__(256, 1)
void gemm_tf32(const float* __restrict__ A, int lda, long sAo, long sAi,
               const float* __restrict__ Bm, int ldb, long sBo, long sBi,
               float* __restrict__ C, int ldc, long sCo, long sCi,
               const float* __restrict__ bias,
               int M, int N, int K, int innerN, float alpha)
{
    int z  = blockIdx.z;
    int zo = z / innerN, zi = z - zo * innerN;
    A  += zo * sAo + zi * sAi;
    Bm += zo * sBo + zi * sBi;
    C  += zo * sCo + zi * sCi;

    __shared__ float As[2][BM * AST];
    constexpr int BSZ = TRANS_B ? (BN * BNT) : (BKT * BNN);
    __shared__ float Bs[2][BSZ];

    const int tid   = threadIdx.x;
    const int mtile = blockIdx.y * BM;
    const int ntile = blockIdx.x * BN;

    const int warp = tid >> 5, lane = tid & 31;
    const int wm = (warp & 3) * 32, wn = (warp >> 2) * 64;
    const int g = lane >> 2, l4 = lane & 3;

    auto loadA = [&](int buf, int k0) {
        #pragma unroll
        for (int i = 0; i < 2; i++) {
            int idx = tid + i * 256;
            int row = idx >> 2;
            int col = (idx & 3) * 4;
            const float* src = A + (long)(mtile + row) * lda + k0 + col;
            cp16(&As[buf][row * AST + col], src, true);   // M%128==0, K%16==0 guaranteed
        }
    };
    auto loadB = [&](int buf, int k0) {
        if constexpr (!TRANS_B) {
            #pragma unroll
            for (int i = 0; i < 2; i++) {
                int idx = tid + i * 256;
                int r = idx >> 5;            // k row 0..15
                int c = (idx & 31) * 4;      // 0..124
                bool valid = (ntile + c) < N;
                const float* src = Bm + (long)(k0 + r) * ldb + ntile + c;
                cp16(&Bs[buf][r * BNN + c], src, valid);
            }
        } else {
            #pragma unroll
            for (int i = 0; i < 2; i++) {
                int idx = tid + i * 256;
                int r = idx >> 2;            // n row 0..127
                int c = (idx & 3) * 4;       // 0..12
                bool valid = (ntile + r) < N;
                const float* src = Bm + (long)(ntile + r) * ldb + k0 + c;
                cp16(&Bs[buf][r * BNT + c], src, valid);
            }
        }
    };

    float acc[2][8][4] = {};

    loadA(0, 0); loadB(0, 0); cp_commit();

    const int nk = K / BKT;
    for (int kt = 0; kt < nk; kt++) {
        int buf = kt & 1;
        if (kt + 1 < nk) { loadA(buf ^ 1, (kt + 1) * BKT); loadB(buf ^ 1, (kt + 1) * BKT); }
        cp_commit();
        cp_wait<1>();
        __syncthreads();

        #pragma unroll
        for (int kk = 0; kk < BKT; kk += 8) {
            uint32_t af[2][4];
            #pragma unroll
            for (int mi = 0; mi < 2; mi++) {
                const float* base = &As[buf][(wm + mi * 16 + g) * AST + kk];
                af[mi][0] = f2tf32(base[l4]);
                af[mi][1] = f2tf32(base[8 * AST + l4]);
                af[mi][2] = f2tf32(base[l4 + 4]);
                af[mi][3] = f2tf32(base[8 * AST + l4 + 4]);
            }
            #pragma unroll
            for (int ni = 0; ni < 8; ni++) {
                int n = wn + ni * 8 + g;
                uint32_t bf[2];
                if constexpr (TRANS_B) {
                    bf[0] = f2tf32(Bs[buf][n * BNT + kk + l4]);
                    bf[1] = f2tf32(Bs[buf][n * BNT + kk + l4 + 4]);
                } else {
                    bf[0] = f2tf32(Bs[buf][(kk + l4) * BNN + n]);
                    bf[1] = f2tf32(Bs[buf][(kk + l4 + 4) * BNN + n]);
                }
                #pragma unroll
                for (int mi = 0; mi < 2; mi++) mma8(acc[mi][ni], af[mi], bf);
            }
        }
        __syncthreads();
    }

    // epilogue
    #pragma unroll
    for (int mi = 0; mi < 2; mi++) {
        #pragma unroll
        for (int ni = 0; ni < 8; ni++) {
            int c0 = ntile + wn + ni * 8 + 2 * l4;
            if (c0 >= N) continue;
            int r0 = mtile + wm + mi * 16 + g;
            float b0 = bias ? bias[c0]     : 0.0f;
            float b1 = bias ? bias[c0 + 1] : 0.0f;
            float x0 = acc[mi][ni][0] * alpha + b0;
            float x1 = acc[mi][ni][1] * alpha + b1;
            float x2 = acc[mi][ni][2] * alpha + b0;
            float x3 = acc[mi][ni][3] * alpha + b1;
            if (EPI == 1) { x0 = gelu_f(x0); x1 = gelu_f(x1); x2 = gelu_f(x2); x3 = gelu_f(x3); }
            float2 v0 = make_float2(x0, x1);
            float2 v1 = make_float2(x2, x3);
            *(float2*)&C[(long)r0 * ldc + c0]       = v0;
            *(float2*)&C[(long)(r0 + 8) * ldc + c0] = v1;
        }
    }
}

// ---------------- embeddings + LN ----------------
__global__ void embed_ln(const int* __restrict__ ids,
                         const float* __restrict__ tok, const float* __restrict__ pos,
                         const float* __restrict__ typ,
                         const float* __restrict__ gam, const float* __restrict__ bet,
                         float* __restrict__ out)
{
    __shared__ float sh[8];
    int i = blockIdx.x;                 // token index
    int s = i % SEQ;
    int tid = threadIdx.x;
    long id = ids[i];
    float v[3]; float ssum = 0.0f;
    #pragma unroll
    for (int j = 0; j < 3; j++) {
        int c = tid + j * 256;
        v[j] = tok[id * HID + c] + pos[(long)s * HID + c] + typ[c];
        ssum += v[j];
    }
    float mean = blk_sum<8>(ssum, sh, tid) * (1.0f / HID);
    float vs = 0.0f;
    #pragma unroll
    for (int j = 0; j < 3; j++) { float d = v[j] - mean; vs += d * d; }
    float var = blk_sum<8>(vs, sh, tid) * (1.0f / HID);
    float inv = rsqrtf(var + 1e-12f);
    #pragma unroll
    for (int j = 0; j < 3; j++) {
        int c = tid + j * 256;
        out[(long)i * HID + c] = (v[j] - mean) * inv * gam[c] + bet[c];
    }
}

// ---------------- residual + LN : out = LN(res + x) ----------------
__global__ void ln_fused(const float* __restrict__ res, const float* __restrict__ x,
                         const float* __restrict__ gam, const float* __restrict__ bet,
                         float* __restrict__ out)
{
    __shared__ float sh[8];
    int row = blockIdx.x;
    int tid = threadIdx.x;
    const float* rp = res + (long)row * HID;
    const float* xp = x   + (long)row * HID;
    float v[3]; float ssum = 0.0f;
    #pragma unroll
    for (int j = 0; j < 3; j++) {
        int c = tid + j * 256;
        v[j] = rp[c] + xp[c];
        ssum += v[j];
    }
    float mean = blk_sum<8>(ssum, sh, tid) * (1.0f / HID);
    float vs = 0.0f;
    #pragma unroll
    for (int j = 0; j < 3; j++) { float d = v[j] - mean; vs += d * d; }
    float var = blk_sum<8>(vs, sh, tid) * (1.0f / HID);
    float inv = rsqrtf(var + 1e-12f);
    #pragma unroll
    for (int j = 0; j < 3; j++) {
        int c = tid + j * 256;
        out[(long)row * HID + c] = (v[j] - mean) * inv * gam[c] + bet[c];
    }
}

// ---------------- masked softmax over last dim (SEQ) ----------------
__global__ void softmax_mask(float* __restrict__ sc, const int* __restrict__ mask)
{
    __shared__ float sh[4];
    long row = blockIdx.x;                       // B*NH*S rows
    int  b   = (int)(row / ((long)NHEADS * SEQ));
    float* p = sc + row * SEQ;
    const int* mrow = mask + (long)b * SEQ;
    int tid = threadIdx.x;
    float v[4];
    #pragma unroll
    for (int j = 0; j < 4; j++) {
        int c = tid + j * 128;
        v[j] = p[c] + (1.0f - (float)mrow[c]) * (-1e9f);
    }
    float mx = blk_max<4>(fmaxf(fmaxf(v[0], v[1]), fmaxf(v[2], v[3])), sh, tid);
    float s = 0.0f;
    #pragma unroll
    for (int j = 0; j < 4; j++) { v[j] = __expf(v[j] - mx); s += v[j]; }
    float tot = blk_sum<4>(s, sh, tid);
    float inv = 1.0f / tot;
    #pragma unroll
    for (int j = 0; j < 4; j++) p[tid + j * 128] = v[j] * inv;
}

// ---------------- span gather + classifier ----------------
__global__ void classifier_k(const float* __restrict__ h, const int* __restrict__ spans,
                             const float* __restrict__ W, const float* __restrict__ bias,
                             float* __restrict__ out)
{
    __shared__ float sh[4 * NLBL];
    int z = blockIdx.x;                  // B*NS
    int b = z / NSPAN;
    int s0 = spans[z * 2], s1 = spans[z * 2 + 1];
    const float* h0 = h + ((long)(b * SEQ + s0)) * HID;
    const float* h1 = h + ((long)(b * SEQ + s1)) * HID;
    float acc[NLBL] = {};
    for (int j = threadIdx.x; j < 2 * HID; j += blockDim.x) {
        float xv = (j < HID) ? h0[j] : h1[j - HID];
        const float* wr = W + (long)j * NLBL;
        #pragma unroll
        for (int c = 0; c < NLBL; c++) acc[c] += xv * wr[c];
    }
    #pragma unroll
    for (int c = 0; c < NLBL; c++) {
        float v = acc[c];
        #pragma unroll
        for (int o = 16; o > 0; o >>= 1) v += __shfl_xor_sync(0xffffffffu, v, o);
        if ((threadIdx.x & 31) == 0) sh[(threadIdx.x >> 5) * NLBL + c] = v;
    }
    __syncthreads();
    if (threadIdx.x < NLBL) {
        float t = sh[threadIdx.x] + sh[NLBL + threadIdx.x]
                + sh[2 * NLBL + threadIdx.x] + sh[3 * NLBL + threadIdx.x];
        out[(long)z * NLBL + threadIdx.x] = t + bias[threadIdx.x];
    }
}

// ---------------- host ----------------
extern "C" void kernel_launch(void* const* d_in, const int* in_sizes, int n_in,
                              void* d_out, int out_size)
{
    const int*   ids   = (const int*)d_in[0];
    const int*   mask  = (const int*)d_in[1];
    const int*   spans = (const int*)d_in[2];
    const float* tok   = (const float*)d_in[3];
    const float* pos   = (const float*)d_in[4];
    const float* typ   = (const float*)d_in[5];
    const float* embg  = (const float*)d_in[6];
    const float* embb  = (const float*)d_in[7];
    const float* Wq = (const float*)d_in[8],  *bq = (const float*)d_in[9];
    const float* Wk = (const float*)d_in[10], *bk = (const float*)d_in[11];
    const float* Wv = (const float*)d_in[12], *bv = (const float*)d_in[13];
    const float* Wo = (const float*)d_in[14], *bo = (const float*)d_in[15];
    const float* l1g = (const float*)d_in[16], *l1b = (const float*)d_in[17];
    const float* W1 = (const float*)d_in[18], *b1 = (const float*)d_in[19];
    const float* W2 = (const float*)d_in[20], *b2 = (const float*)d_in[21];
    const float* l2g = (const float*)d_in[22], *l2b = (const float*)d_in[23];
    const float* clsW = (const float*)d_in[24], *clsb = (const float*)d_in[25];
    float* out = (float*)d_out;

    float *h, *h2, *q, *k, *v, *ctx, *tmp, *ff, *sc;
    cudaGetSymbolAddress((void**)&h,   g_h);
    cudaGetSymbolAddress((void**)&h2,  g_h2);
    cudaGetSymbolAddress((void**)&q,   g_q);
    cudaGetSymbolAddress((void**)&k,   g_k);
    cudaGetSymbolAddress((void**)&v,   g_v);
    cudaGetSymbolAddress((void**)&ctx, g_ctx);
    cudaGetSymbolAddress((void**)&tmp, g_tmp);
    cudaGetSymbolAddress((void**)&ff,  g_ff);
    cudaGetSymbolAddress((void**)&sc,  g_sc);

    embed_ln<<<NTOK, 256>>>(ids, tok, pos, typ, embg, embb, h);

    const dim3 blk(256);
    const dim3 gq (HID / BN,  NTOK / BM, 1);                 // [16384,768] x [768,768]
    const dim3 gs (SEQ / BN,  SEQ  / BM, BATCH * NHEADS);    // scores
    const dim3 gc (1,         SEQ  / BM, BATCH * NHEADS);    // ctx (N=64)
    const dim3 gf1(FFD / BN,  NTOK / BM, 1);

    for (int l = 0; l < NLAYER; l++) {
        const float* wq = Wq + (long)l * HID * HID;
        const float* wk = Wk + (long)l * HID * HID;
        const float* wv = Wv + (long)l * HID * HID;
        const float* wo = Wo + (long)l * HID * HID;
        const float* w1 = W1 + (long)l * HID * FFD;
        const float* w2 = W2 + (long)l * FFD * HID;

        gemm_tf32<false,0><<<gq, blk>>>(h, HID, 0, 0, wq, HID, 0, 0,
                                        q, HID, 0, 0, bq + l * HID,
                                        NTOK, HID, HID, 1, 1.0f);
        gemm_tf32<false,0><<<gq, blk>>>(h, HID, 0, 0, wk, HID, 0, 0,
                                        k, HID, 0, 0, bk + l * HID,
                                        NTOK, HID, HID, 1, 1.0f);
        gemm_tf32<false,0><<<gq, blk>>>(h, HID, 0, 0, wv, HID, 0, 0,
                                        v, HID, 0, 0, bv + l * HID,
                                        NTOK, HID, HID, 1, 1.0f);

        // scores[b,hd] = (Q @ K^T) * 0.125     (NT GEMM, batched over B*NH)
        gemm_tf32<true,0><<<gs, blk>>>(q, HID, (long)SEQ * HID, DHEAD,
                                       k, HID, (long)SEQ * HID, DHEAD,
                                       sc, SEQ, (long)NHEADS * SEQ * SEQ, (long)SEQ * SEQ,
                                       nullptr, SEQ, SEQ, DHEAD, NHEADS, 0.125f);

        softmax_mask<<<BATCH * NHEADS * SEQ, 128>>>(sc, mask);

        // ctx[b,hd] = P @ V   (N=64, written interleaved back into [B,S,H])
        gemm_tf32<false,0><<<gc, blk>>>(sc, SEQ, (long)NHEADS * SEQ * SEQ, (long)SEQ * SEQ,
                                        v, HID, (long)SEQ * HID, DHEAD,
                                        ctx, HID, (long)SEQ * HID, DHEAD,
                                        nullptr, SEQ, DHEAD, SEQ, NHEADS, 1.0f);

        gemm_tf32<false,0><<<gq, blk>>>(ctx, HID, 0, 0, wo, HID, 0, 0,
                                        tmp, HID, 0, 0, bo + l * HID,
                                        NTOK, HID, HID, 1, 1.0f);

        ln_fused<<<NTOK, 256>>>(h, tmp, l1g + l * HID, l1b + l * HID, h2);

        gemm_tf32<false,1><<<gf1, blk>>>(h2, HID, 0, 0, w1, FFD, 0, 0,
                                         ff, FFD, 0, 0, b1 + l * FFD,
                                         NTOK, FFD, HID, 1, 1.0f);

        gemm_tf32<false,0><<<gq, blk>>>(ff, FFD, 0, 0, w2, HID, 0, 0,
                                        tmp, HID, 0, 0, b2 + l * HID,
                                        NTOK, HID, FFD, 1, 1.0f);

        ln_fused<<<NTOK, 256>>>(h2, tmp, l2g + l * HID, l2b + l * HID, h);
    }

    classifier_k<<<BATCH * NSPAN, 128>>>(h, spans, clsW, clsb, out);
    (void)in_sizes; (void)n_in; (void)out_size;
}

// round 2
// speedup vs baseline: 1.0688x; 1.0688x over previous
#include <cuda_runtime.h>
#include <cuda_bf16.h>
#include <cstdint>
#include <math.h>

// ---------------- problem constants ----------------
#define BATCH   32
#define SEQ     512
#define NTOK    (BATCH*SEQ)      // 16384
#define HID     768
#define FFD     3072
#define NHEADS  12
#define DHEAD   64
#define NLAYER  12
#define NSPAN   256
#define NLBL    9

// ---------------- scratch (device globals: allocation-free) ----------------
__device__ float g_h  [NTOK*HID];
__device__ float g_h2 [NTOK*HID];
__device__ float g_q  [NTOK*HID];
__device__ float g_k  [NTOK*HID];
__device__ float g_v  [NTOK*HID];
__device__ float g_ctx[NTOK*HID];
__device__ float g_tmp[NTOK*HID];
__device__ float g_ff [NTOK*FFD];

// ---------------- small helpers ----------------
__device__ __forceinline__ uint32_t f2tf32(float x) {
    uint32_t r;
    asm("cvt.rna.tf32.f32 %0, %1;\n" : "=r"(r) : "f"(x));
    return r;
}

__device__ __forceinline__ void mma8(float* d, const uint32_t* a, const uint32_t* b) {
    asm volatile(
        "mma.sync.aligned.m16n8k8.row.col.f32.tf32.tf32.f32 "
        "{%0,%1,%2,%3}, {%4,%5,%6,%7}, {%8,%9}, {%0,%1,%2,%3};\n"
        : "+f"(d[0]), "+f"(d[1]), "+f"(d[2]), "+f"(d[3])
        : "r"(a[0]), "r"(a[1]), "r"(a[2]), "r"(a[3]), "r"(b[0]), "r"(b[1]));
}

__device__ __forceinline__ void cp16(void* dst, const void* src, bool valid) {
    uint32_t d = (uint32_t)__cvta_generic_to_shared(dst);
    int sz = valid ? 16 : 0;
    asm volatile("cp.async.cg.shared.global [%0], [%1], 16, %2;\n"
                 :: "r"(d), "l"(src), "r"(sz));
}
__device__ __forceinline__ void cp_commit() { asm volatile("cp.async.commit_group;\n"); }
template<int N> __device__ __forceinline__ void cp_wait() {
    asm volatile("cp.async.wait_group %0;\n" :: "n"(N));
}

__device__ __forceinline__ float gelu_f(float x) {
    return 0.5f * x * (1.0f + erff(x * 0.7071067811865476f));
}

template<int NWARP>
__device__ __forceinline__ float blk_sum(float v, float* sh, int tid) {
    #pragma unroll
    for (int o = 16; o > 0; o >>= 1) v += __shfl_xor_sync(0xffffffffu, v, o);
    if ((tid & 31) == 0) sh[tid >> 5] = v;
    __syncthreads();
    float t = (tid < NWARP) ? sh[tid] : 0.0f;
    #pragma unroll
    for (int o = NWARP >> 1; o > 0; o >>= 1) t += __shfl_xor_sync(0xffffffffu, t, o);
    if (tid == 0) sh[0] = t;
    __syncthreads();
    float r = sh[0];
    __syncthreads();
    return r;
}

// ---------------- generic TF32 GEMM ----------------
#define BM 128
#define BN 128
#define BKT 16
#define AST 20     // BK + 4 pad
#define BNN 136    // BN + 8 pad
#define BNT 20     // BK + 4 pad

template<bool TRANS_B, int EPI>
__global__ __launch_bounds__(256, 2)
void gemm_tf32(const float* __restrict__ A, int lda, long sAo, long sAi,
               const float* __restrict__ Bm, int ldb, long sBo, long sBi,
               float* __restrict__ C, int ldc, long sCo, long sCi,
               const float* __restrict__ bias,
               int M, int N, int K, int innerN, float alpha)
{
    int z  = blockIdx.z;
    int zo = z / innerN, zi = z - zo * innerN;
    A  += zo * sAo + zi * sAi;
    Bm += zo * sBo + zi * sBi;
    C  += zo * sCo + zi * sCi;

    __shared__ float As[2][BM * AST];
    constexpr int BSZ = TRANS_B ? (BN * BNT) : (BKT * BNN);
    __shared__ float Bs[2][BSZ];

    const int tid   = threadIdx.x;
    const int mtile = blockIdx.y * BM;
    const int ntile = blockIdx.x * BN;

    const int warp = tid >> 5, lane = tid & 31;
    const int wm = (warp & 3) * 32, wn = (warp >> 2) * 64;
    const int g = lane >> 2, l4 = lane & 3;

    auto loadA = [&](int buf, int k0) {
        #pragma unroll
        for (int i = 0; i < 2; i++) {
            int idx = tid + i * 256;
            int row = idx >> 2;
            int col = (idx & 3) * 4;
            const float* src = A + (long)(mtile + row) * lda + k0 + col;
            cp16(&As[buf][row * AST + col], src, true);
        }
    };
    auto loadB = [&](int buf, int k0) {
        if constexpr (!TRANS_B) {
            #pragma unroll
            for (int i = 0; i < 2; i++) {
                int idx = tid + i * 256;
                int r = idx >> 5;
                int c = (idx & 31) * 4;
                bool valid = (ntile + c) < N;
                const float* src = Bm + (long)(k0 + r) * ldb + ntile + c;
                cp16(&Bs[buf][r * BNN + c], src, valid);
            }
        } else {
            #pragma unroll
            for (int i = 0; i < 2; i++) {
                int idx = tid + i * 256;
                int r = idx >> 2;
                int c = (idx & 3) * 4;
                bool valid = (ntile + r) < N;
                const float* src = Bm + (long)(ntile + r) * ldb + k0 + c;
                cp16(&Bs[buf][r * BNT + c], src, valid);
            }
        }
    };

    float acc[2][8][4] = {};

    loadA(0, 0); loadB(0, 0); cp_commit();

    const int nk = K / BKT;
    for (int kt = 0; kt < nk; kt++) {
        int buf = kt & 1;
        if (kt + 1 < nk) { loadA(buf ^ 1, (kt + 1) * BKT); loadB(buf ^ 1, (kt + 1) * BKT); }
        cp_commit();
        cp_wait<1>();
        __syncthreads();

        #pragma unroll
        for (int kk = 0; kk < BKT; kk += 8) {
            uint32_t af[2][4];
            #pragma unroll
            for (int mi = 0; mi < 2; mi++) {
                const float* base = &As[buf][(wm + mi * 16 + g) * AST + kk];
                af[mi][0] = f2tf32(base[l4]);
                af[mi][1] = f2tf32(base[8 * AST + l4]);
                af[mi][2] = f2tf32(base[l4 + 4]);
                af[mi][3] = f2tf32(base[8 * AST + l4 + 4]);
            }
            #pragma unroll
            for (int ni = 0; ni < 8; ni++) {
                int n = wn + ni * 8 + g;
                uint32_t bf[2];
                if constexpr (TRANS_B) {
                    bf[0] = f2tf32(Bs[buf][n * BNT + kk + l4]);
                    bf[1] = f2tf32(Bs[buf][n * BNT + kk + l4 + 4]);
                } else {
                    bf[0] = f2tf32(Bs[buf][(kk + l4) * BNN + n]);
                    bf[1] = f2tf32(Bs[buf][(kk + l4 + 4) * BNN + n]);
                }
                #pragma unroll
                for (int mi = 0; mi < 2; mi++) mma8(acc[mi][ni], af[mi], bf);
            }
        }
        __syncthreads();
    }

    #pragma unroll
    for (int mi = 0; mi < 2; mi++) {
        #pragma unroll
        for (int ni = 0; ni < 8; ni++) {
            int c0 = ntile + wn + ni * 8 + 2 * l4;
            if (c0 >= N) continue;
            int r0 = mtile + wm + mi * 16 + g;
            float b0 = bias ? bias[c0]     : 0.0f;
            float b1 = bias ? bias[c0 + 1] : 0.0f;
            float x0 = acc[mi][ni][0] * alpha + b0;
            float x1 = acc[mi][ni][1] * alpha + b1;
            float x2 = acc[mi][ni][2] * alpha + b0;
            float x3 = acc[mi][ni][3] * alpha + b1;
            if (EPI == 1) { x0 = gelu_f(x0); x1 = gelu_f(x1); x2 = gelu_f(x2); x3 = gelu_f(x3); }
            *(float2*)&C[(long)r0 * ldc + c0]       = make_float2(x0, x1);
            *(float2*)&C[(long)(r0 + 8) * ldc + c0] = make_float2(x2, x3);
        }
    }
}

// ---------------- fused flash attention ----------------
// One block per (q-tile of 128 rows, batch*head). KV streamed in 64-row steps.
#define FBQ 128
#define FBK 64
#define QST 68     // DHEAD + 4
#define KST 68
#define PST 68     // FBK + 4

struct FlashSmem {
    float Qs[FBQ * QST];
    float Ks[FBK * KST];
    float Vs[FBK * KST];
    float Ps[FBQ * PST];
    float pm[FBQ * 2];
    float ps[FBQ * 2];
    float m_s[FBQ];
    float l_s[FBQ];
    float mb_s[FBK];
};
#define FSMEM ((int)sizeof(FlashSmem))

__global__ __launch_bounds__(256, 2)
void flash_attn(const float* __restrict__ q, const float* __restrict__ k,
                const float* __restrict__ v, const int* __restrict__ mask,
                float* __restrict__ ctx)
{
    extern __shared__ char fsm_raw[];
    FlashSmem* sm = (FlashSmem*)fsm_raw;

    const int tid = threadIdx.x;
    const int qt  = blockIdx.x;           // 0..3
    const int bh  = blockIdx.y;           // 0..383
    const int b = bh / NHEADS, hd = bh - b * NHEADS;
    const long base = (long)b * SEQ * HID + (long)hd * DHEAD;
    const float* Qg = q + base + (long)qt * FBQ * HID;
    const float* Kg = k + base;
    const float* Vg = v + base;

    const int warp = tid >> 5, lane = tid & 31;
    const int wm  = (warp & 3) * 32;
    const int wnS = (warp >> 2) * 32;     // S col half (0 / 32)
    const int wnO = (warp >> 2) * 32;     // O col half
    const int wcol = warp >> 2;
    const int g = lane >> 2, l4 = lane & 3;

    // load Q tile (128 x 64): 2048 float4 over 256 threads
    #pragma unroll
    for (int i = 0; i < 8; i++) {
        int idx = tid + i * 256;
        int r = idx >> 4;
        int c = (idx & 15) * 4;
        cp16(&sm->Qs[r * QST + c], Qg + (long)r * HID + c, true);
    }
    cp_commit();

    if (tid < FBQ) { sm->m_s[tid] = -3.4e38f; sm->l_s[tid] = 0.0f; }

    float accO[2][4][4] = {};

    for (int j = 0; j < SEQ / FBK; j++) {
        __syncthreads();   // prior-iter smem reads done (incl. init on j=0)
        // load K,V tiles (64 x 64 each): 1024 float4 each
        #pragma unroll
        for (int i = 0; i < 4; i++) {
            int idx = tid + i * 256;
            int r = idx >> 4;
            int c = (idx & 15) * 4;
            cp16(&sm->Ks[r * KST + c], Kg + (long)(j * FBK + r) * HID + c, true);
        }
        #pragma unroll
        for (int i = 0; i < 4; i++) {
            int idx = tid + i * 256;
            int r = idx >> 4;
            int c = (idx & 15) * 4;
            cp16(&sm->Vs[r * KST + c], Vg + (long)(j * FBK + r) * HID + c, true);
        }
        if (tid < FBK)
            sm->mb_s[tid] = (1.0f - (float)mask[b * SEQ + j * FBK + tid]) * (-1e9f);
        cp_commit();
        cp_wait<0>();
        __syncthreads();

        // ---- S = (Q @ K^T) * scale + bias ----
        float accS[2][4][4] = {};
        #pragma unroll
        for (int kk = 0; kk < DHEAD; kk += 8) {
            uint32_t af[2][4];
            #pragma unroll
            for (int mi = 0; mi < 2; mi++) {
                const float* bp = &sm->Qs[(wm + mi * 16 + g) * QST + kk];
                af[mi][0] = f2tf32(bp[l4]);
                af[mi][1] = f2tf32(bp[8 * QST + l4]);
                af[mi][2] = f2tf32(bp[l4 + 4]);
                af[mi][3] = f2tf32(bp[8 * QST + l4 + 4]);
            }
            #pragma unroll
            for (int ni = 0; ni < 4; ni++) {
                int n = wnS + ni * 8 + g;
                uint32_t bf[2];
                bf[0] = f2tf32(sm->Ks[n * KST + kk + l4]);
                bf[1] = f2tf32(sm->Ks[n * KST + kk + l4 + 4]);
                #pragma unroll
                for (int mi = 0; mi < 2; mi++) mma8(accS[mi][ni], af[mi], bf);
            }
        }
        #pragma unroll
        for (int mi = 0; mi < 2; mi++)
            #pragma unroll
            for (int ni = 0; ni < 4; ni++) {
                int c0 = wnS + ni * 8 + 2 * l4;
                float bb0 = sm->mb_s[c0], bb1 = sm->mb_s[c0 + 1];
                accS[mi][ni][0] = accS[mi][ni][0] * 0.125f + bb0;
                accS[mi][ni][1] = accS[mi][ni][1] * 0.125f + bb1;
                accS[mi][ni][2] = accS[mi][ni][2] * 0.125f + bb0;
                accS[mi][ni][3] = accS[mi][ni][3] * 0.125f + bb1;
            }

        // ---- online softmax ----
        float m_old[2][2];
        #pragma unroll
        for (int mi = 0; mi < 2; mi++) {
            m_old[mi][0] = sm->m_s[wm + mi * 16 + g];
            m_old[mi][1] = sm->m_s[wm + mi * 16 + g + 8];
        }
        #pragma unroll
        for (int mi = 0; mi < 2; mi++) {
            float v0 = -3.4e38f, v1 = -3.4e38f;
            #pragma unroll
            for (int ni = 0; ni < 4; ni++) {
                v0 = fmaxf(v0, fmaxf(accS[mi][ni][0], accS[mi][ni][1]));
                v1 = fmaxf(v1, fmaxf(accS[mi][ni][2], accS[mi][ni][3]));
            }
            v0 = fmaxf(v0, __shfl_xor_sync(~0u, v0, 1));
            v0 = fmaxf(v0, __shfl_xor_sync(~0u, v0, 2));
            v1 = fmaxf(v1, __shfl_xor_sync(~0u, v1, 1));
            v1 = fmaxf(v1, __shfl_xor_sync(~0u, v1, 2));
            if (l4 == 0) {
                sm->pm[(wm + mi * 16 + g) * 2 + wcol]     = v0;
                sm->pm[(wm + mi * 16 + g + 8) * 2 + wcol] = v1;
            }
        }
        __syncthreads();
        float m_new[2][2];
        #pragma unroll
        for (int mi = 0; mi < 2; mi++) {
            int r0 = wm + mi * 16 + g;
            m_new[mi][0] = fmaxf(m_old[mi][0], fmaxf(sm->pm[r0 * 2], sm->pm[r0 * 2 + 1]));
            m_new[mi][1] = fmaxf(m_old[mi][1], fmaxf(sm->pm[(r0 + 8) * 2], sm->pm[(r0 + 8) * 2 + 1]));
        }
        #pragma unroll
        for (int mi = 0; mi < 2; mi++) {
            float s0 = 0.0f, s1 = 0.0f;
            #pragma unroll
            for (int ni = 0; ni < 4; ni++) {
                accS[mi][ni][0] = __expf(accS[mi][ni][0] - m_new[mi][0]);
                accS[mi][ni][1] = __expf(accS[mi][ni][1] - m_new[mi][0]);
                accS[mi][ni][2] = __expf(accS[mi][ni][2] - m_new[mi][1]);
                accS[mi][ni][3] = __expf(accS[mi][ni][3] - m_new[mi][1]);
                s0 += accS[mi][ni][0] + accS[mi][ni][1];
                s1 += accS[mi][ni][2] + accS[mi][ni][3];
            }
            s0 += __shfl_xor_sync(~0u, s0, 1);
            s0 += __shfl_xor_sync(~0u, s0, 2);
            s1 += __shfl_xor_sync(~0u, s1, 1);
            s1 += __shfl_xor_sync(~0u, s1, 2);
            if (l4 == 0) {
                sm->ps[(wm + mi * 16 + g) * 2 + wcol]     = s0;
                sm->ps[(wm + mi * 16 + g + 8) * 2 + wcol] = s1;
            }
        }
        __syncthreads();
        if (wcol == 0 && l4 == 0) {
            #pragma unroll
            for (int mi = 0; mi < 2; mi++) {
                int r0 = wm + mi * 16 + g;
                float a0 = __expf(m_old[mi][0] - m_new[mi][0]);
                sm->l_s[r0] = sm->l_s[r0] * a0 + sm->ps[r0 * 2] + sm->ps[r0 * 2 + 1];
                sm->m_s[r0] = m_new[mi][0];
                int r1 = r0 + 8;
                float a1 = __expf(m_old[mi][1] - m_new[mi][1]);
                sm->l_s[r1] = sm->l_s[r1] * a1 + sm->ps[r1 * 2] + sm->ps[r1 * 2 + 1];
                sm->m_s[r1] = m_new[mi][1];
            }
        }
        // rescale O (same row mapping as S)
        #pragma unroll
        for (int mi = 0; mi < 2; mi++) {
            float a0 = __expf(m_old[mi][0] - m_new[mi][0]);
            float a1 = __expf(m_old[mi][1] - m_new[mi][1]);
            #pragma unroll
            for (int ni = 0; ni < 4; ni++) {
                accO[mi][ni][0] *= a0; accO[mi][ni][1] *= a0;
                accO[mi][ni][2] *= a1; accO[mi][ni][3] *= a1;
            }
        }
        // write P to smem
        #pragma unroll
        for (int mi = 0; mi < 2; mi++)
            #pragma unroll
            for (int ni = 0; ni < 4; ni++) {
                int r0 = wm + mi * 16 + g, c0 = wnS + ni * 8 + 2 * l4;
                sm->Ps[r0 * PST + c0]           = accS[mi][ni][0];
                sm->Ps[r0 * PST + c0 + 1]       = accS[mi][ni][1];
                sm->Ps[(r0 + 8) * PST + c0]     = accS[mi][ni][2];
                sm->Ps[(r0 + 8) * PST + c0 + 1] = accS[mi][ni][3];
            }
        __syncthreads();
        // ---- O += P @ V ----
        #pragma unroll
        for (int kk = 0; kk < FBK; kk += 8) {
            uint32_t af[2][4];
            #pragma unroll
            for (int mi = 0; mi < 2; mi++) {
                const float* bp = &sm->Ps[(wm + mi * 16 + g) * PST + kk];
                af[mi][0] = f2tf32(bp[l4]);
                af[mi][1] = f2tf32(bp[8 * PST + l4]);
                af[mi][2] = f2tf32(bp[l4 + 4]);
                af[mi][3] = f2tf32(bp[8 * PST + l4 + 4]);
            }
            #pragma unroll
            for (int ni = 0; ni < 4; ni++) {
                int n = wnO + ni * 8 + g;
                uint32_t bf[2];
                bf[0] = f2tf32(sm->Vs[(kk + l4) * KST + n]);
                bf[1] = f2tf32(sm->Vs[(kk + l4 + 4) * KST + n]);
                #pragma unroll
                for (int mi = 0; mi < 2; mi++) mma8(accO[mi][ni], af[mi], bf);
            }
        }
    }

    __syncthreads();
    float* Cg = ctx + base + (long)qt * FBQ * HID;
    #pragma unroll
    for (int mi = 0; mi < 2; mi++) {
        int r0 = wm + mi * 16 + g;
        float inv0 = 1.0f / sm->l_s[r0];
        float inv1 = 1.0f / sm->l_s[r0 + 8];
        #pragma unroll
        for (int ni = 0; ni < 4; ni++) {
            int c0 = wnO + ni * 8 + 2 * l4;
            *(float2*)&Cg[(long)r0 * HID + c0] =
                make_float2(accO[mi][ni][0] * inv0, accO[mi][ni][1] * inv0);
            *(float2*)&Cg[(long)(r0 + 8) * HID + c0] =
                make_float2(accO[mi][ni][2] * inv1, accO[mi][ni][3] * inv1);
        }
    }
}

// ---------------- embeddings + LN ----------------
__global__ void embed_ln(const int* __restrict__ ids,
                         const float* __restrict__ tok, const float* __restrict__ pos,
                         const float* __restrict__ typ,
                         const float* __restrict__ gam, const float* __restrict__ bet,
                         float* __restrict__ out)
{
    __shared__ float sh[8];
    int i = blockIdx.x;
    int s = i % SEQ;
    int tid = threadIdx.x;
    long id = ids[i];
    float v[3]; float ssum = 0.0f;
    #pragma unroll
    for (int j = 0; j < 3; j++) {
        int c = tid + j * 256;
        v[j] = tok[id * HID + c] + pos[(long)s * HID + c] + typ[c];
        ssum += v[j];
    }
    float mean = blk_sum<8>(ssum, sh, tid) * (1.0f / HID);
    float vs = 0.0f;
    #pragma unroll
    for (int j = 0; j < 3; j++) { float d = v[j] - mean; vs += d * d; }
    float var = blk_sum<8>(vs, sh, tid) * (1.0f / HID);
    float inv = rsqrtf(var + 1e-12f);
    #pragma unroll
    for (int j = 0; j < 3; j++) {
        int c = tid + j * 256;
        out[(long)i * HID + c] = (v[j] - mean) * inv * gam[c] + bet[c];
    }
}

// ---------------- residual + LN ----------------
__global__ void ln_fused(const float* __restrict__ res, const float* __restrict__ x,
                         const float* __restrict__ gam, const float* __restrict__ bet,
                         float* __restrict__ out)
{
    __shared__ float sh[8];
    int row = blockIdx.x;
    int tid = threadIdx.x;
    const float* rp = res + (long)row * HID;
    const float* xp = x   + (long)row * HID;
    float v[3]; float ssum = 0.0f;
    #pragma unroll
    for (int j = 0; j < 3; j++) {
        int c = tid + j * 256;
        v[j] = rp[c] + xp[c];
        ssum += v[j];
    }
    float mean = blk_sum<8>(ssum, sh, tid) * (1.0f / HID);
    float vs = 0.0f;
    #pragma unroll
    for (int j = 0; j < 3; j++) { float d = v[j] - mean; vs += d * d; }
    float var = blk_sum<8>(vs, sh, tid) * (1.0f / HID);
    float inv = rsqrtf(var + 1e-12f);
    #pragma unroll
    for (int j = 0; j < 3; j++) {
        int c = tid + j * 256;
        out[(long)row * HID + c] = (v[j] - mean) * inv * gam[c] + bet[c];
    }
}

// ---------------- span gather + classifier ----------------
__global__ void classifier_k(const float* __restrict__ h, const int* __restrict__ spans,
                             const float* __restrict__ W, const float* __restrict__ bias,
                             float* __restrict__ out)
{
    __shared__ float sh[4 * NLBL];
    int z = blockIdx.x;
    int b = z / NSPAN;
    int s0 = spans[z * 2], s1 = spans[z * 2 + 1];
    const float* h0 = h + ((long)(b * SEQ + s0)) * HID;
    const float* h1 = h + ((long)(b * SEQ + s1)) * HID;
    float acc[NLBL] = {};
    for (int j = threadIdx.x; j < 2 * HID; j += blockDim.x) {
        float xv = (j < HID) ? h0[j] : h1[j - HID];
        const float* wr = W + (long)j * NLBL;
        #pragma unroll
        for (int c = 0; c < NLBL; c++) acc[c] += xv * wr[c];
    }
    #pragma unroll
    for (int c = 0; c < NLBL; c++) {
        float v = acc[c];
        #pragma unroll
        for (int o = 16; o > 0; o >>= 1) v += __shfl_xor_sync(0xffffffffu, v, o);
        if ((threadIdx.x & 31) == 0) sh[(threadIdx.x >> 5) * NLBL + c] = v;
    }
    __syncthreads();
    if (threadIdx.x < NLBL) {
        float t = sh[threadIdx.x] + sh[NLBL + threadIdx.x]
                + sh[2 * NLBL + threadIdx.x] + sh[3 * NLBL + threadIdx.x];
        out[(long)z * NLBL + threadIdx.x] = t + bias[threadIdx.x];
    }
}

// ---------------- host ----------------
extern "C" void kernel_launch(void* const* d_in, const int* in_sizes, int n_in,
                              void* d_out, int out_size)
{
    const int*   ids   = (const int*)d_in[0];
    const int*   mask  = (const int*)d_in[1];
    const int*   spans = (const int*)d_in[2];
    const float* tok   = (const float*)d_in[3];
    const float* pos   = (const float*)d_in[4];
    const float* typ   = (const float*)d_in[5];
    const float* embg  = (const float*)d_in[6];
    const float* embb  = (const float*)d_in[7];
    const float* Wq = (const float*)d_in[8],  *bq = (const float*)d_in[9];
    const float* Wk = (const float*)d_in[10], *bk = (const float*)d_in[11];
    const float* Wv = (const float*)d_in[12], *bv = (const float*)d_in[13];
    const float* Wo = (const float*)d_in[14], *bo = (const float*)d_in[15];
    const float* l1g = (const float*)d_in[16], *l1b = (const float*)d_in[17];
    const float* W1 = (const float*)d_in[18], *b1 = (const float*)d_in[19];
    const float* W2 = (const float*)d_in[20], *b2 = (const float*)d_in[21];
    const float* l2g = (const float*)d_in[22], *l2b = (const float*)d_in[23];
    const float* clsW = (const float*)d_in[24], *clsb = (const float*)d_in[25];
    float* out = (float*)d_out;

    float *h, *h2, *q, *k, *v, *ctx, *tmp, *ff;
    cudaGetSymbolAddress((void**)&h,   g_h);
    cudaGetSymbolAddress((void**)&h2,  g_h2);
    cudaGetSymbolAddress((void**)&q,   g_q);
    cudaGetSymbolAddress((void**)&k,   g_k);
    cudaGetSymbolAddress((void**)&v,   g_v);
    cudaGetSymbolAddress((void**)&ctx, g_ctx);
    cudaGetSymbolAddress((void**)&tmp, g_tmp);
    cudaGetSymbolAddress((void**)&ff,  g_ff);

    cudaFuncSetAttribute(flash_attn, cudaFuncAttributeMaxDynamicSharedMemorySize, FSMEM);

    embed_ln<<<NTOK, 256>>>(ids, tok, pos, typ, embg, embb, h);

    const dim3 blk(256);
    const dim3 gq (HID / BN,  NTOK / BM, 1);
    const dim3 gf1(FFD / BN,  NTOK / BM, 1);
    const dim3 gattn(SEQ / FBQ, BATCH * NHEADS);

    for (int l = 0; l < NLAYER; l++) {
        const float* wq = Wq + (long)l * HID * HID;
        const float* wk = Wk + (long)l * HID * HID;
        const float* wv = Wv + (long)l * HID * HID;
        const float* wo = Wo + (long)l * HID * HID;
        const float* w1 = W1 + (long)l * HID * FFD;
        const float* w2 = W2 + (long)l * FFD * HID;

        gemm_tf32<false,0><<<gq, blk>>>(h, HID, 0, 0, wq, HID, 0, 0,
                                        q, HID, 0, 0, bq + l * HID,
                                        NTOK, HID, HID, 1, 1.0f);
        gemm_tf32<false,0><<<gq, blk>>>(h, HID, 0, 0, wk, HID, 0, 0,
                                        k, HID, 0, 0, bk + l * HID,
                                        NTOK, HID, HID, 1, 1.0f);
        gemm_tf32<false,0><<<gq, blk>>>(h, HID, 0, 0, wv, HID, 0, 0,
                                        v, HID, 0, 0, bv + l * HID,
                                        NTOK, HID, HID, 1, 1.0f);

        flash_attn<<<gattn, 256, FSMEM>>>(q, k, v, mask, ctx);

        gemm_tf32<false,0><<<gq, blk>>>(ctx, HID, 0, 0, wo, HID, 0, 0,
                                        tmp, HID, 0, 0, bo + l * HID,
                                        NTOK, HID, HID, 1, 1.0f);

        ln_fused<<<NTOK, 256>>>(h, tmp, l1g + l * HID, l1b + l * HID, h2);

        gemm_tf32<false,1><<<gf1, blk>>>(h2, HID, 0, 0, w1, FFD, 0, 0,
                                         ff, FFD, 0, 0, b1 + l * FFD,
                                         NTOK, FFD, HID, 1, 1.0f);

        gemm_tf32<false,0><<<gq, blk>>>(ff, FFD, 0, 0, w2, HID, 0, 0,
                                        tmp, HID, 0, 0, b2 + l * HID,
                                        NTOK, HID, FFD, 1, 1.0f);

        ln_fused<<<NTOK, 256>>>(h2, tmp, l2g + l * HID, l2b + l * HID, h);
    }

    classifier_k<<<BATCH * NSPAN, 128>>>(h, spans, clsW, clsb, out);
    (void)in_sizes; (void)n_in; (void)out_size;
}

// round 3
// speedup vs baseline: 1.0697x; 1.0008x over previous
#include <cuda_runtime.h>
#include <cuda_bf16.h>
#include <cstdint>
#include <math.h>

// ---------------- problem constants ----------------
#define BATCH   32
#define SEQ     512
#define NTOK    (BATCH*SEQ)      // 16384
#define HID     768
#define FFD     3072
#define NHEADS  12
#define DHEAD   64
#define NLAYER  12
#define NSPAN   256
#define NLBL    9

// ---------------- scratch (device globals: allocation-free) ----------------
__device__ float g_h  [NTOK*HID];
__device__ float g_h2 [NTOK*HID];
__device__ float g_q  [NTOK*HID];
__device__ float g_k  [NTOK*HID];
__device__ float g_v  [NTOK*HID];
__device__ float g_ctx[NTOK*HID];
__device__ float g_tmp[NTOK*HID];
__device__ float g_ff [NTOK*FFD];

// ---------------- small helpers ----------------
__device__ __forceinline__ uint32_t f2tf32(float x) {
    uint32_t r;
    asm("cvt.rna.tf32.f32 %0, %1;\n" : "=r"(r) : "f"(x));
    return r;
}

__device__ __forceinline__ void mma8(float* d, const uint32_t* a, const uint32_t* b) {
    asm volatile(
        "mma.sync.aligned.m16n8k8.row.col.f32.tf32.tf32.f32 "
        "{%0,%1,%2,%3}, {%4,%5,%6,%7}, {%8,%9}, {%0,%1,%2,%3};\n"
        : "+f"(d[0]), "+f"(d[1]), "+f"(d[2]), "+f"(d[3])
        : "r"(a[0]), "r"(a[1]), "r"(a[2]), "r"(a[3]), "r"(b[0]), "r"(b[1]));
}

__device__ __forceinline__ void cp16(void* dst, const void* src, bool valid) {
    uint32_t d = (uint32_t)__cvta_generic_to_shared(dst);
    int sz = valid ? 16 : 0;
    asm volatile("cp.async.cg.shared.global [%0], [%1], 16, %2;\n"
                 :: "r"(d), "l"(src), "r"(sz));
}
__device__ __forceinline__ void cp_commit() { asm volatile("cp.async.commit_group;\n"); }
template<int N> __device__ __forceinline__ void cp_wait() {
    asm volatile("cp.async.wait_group %0;\n" :: "n"(N));
}

__device__ __forceinline__ float gelu_f(float x) {
    return 0.5f * x * (1.0f + erff(x * 0.7071067811865476f));
}

template<int NWARP>
__device__ __forceinline__ float blk_sum(float v, float* sh, int tid) {
    #pragma unroll
    for (int o = 16; o > 0; o >>= 1) v += __shfl_xor_sync(0xffffffffu, v, o);
    if ((tid & 31) == 0) sh[tid >> 5] = v;
    __syncthreads();
    float t = (tid < NWARP) ? sh[tid] : 0.0f;
    #pragma unroll
    for (int o = NWARP >> 1; o > 0; o >>= 1) t += __shfl_xor_sync(0xffffffffu, t, o);
    if (tid == 0) sh[0] = t;
    __syncthreads();
    float r = sh[0];
    __syncthreads();
    return r;
}

// ---------------- generic TF32 GEMM ----------------
#define BM 128
#define BN 128
#define BKT 16
#define AST 20     // BK + 4 pad
#define BNN 136    // BN + 8 pad
#define BNT 20     // BK + 4 pad

template<bool TRANS_B, int EPI>
__global__ __launch_bounds__(256, 2)
void gemm_tf32(const float* __restrict__ A, int lda, long sAo, long sAi,
               const float* __restrict__ Bm, int ldb, long sBo, long sBi,
               float* __restrict__ C, int ldc, long sCo, long sCi,
               const float* __restrict__ bias,
               int M, int N, int K, int innerN, float alpha)
{
    int z  = blockIdx.z;
    int zo = z / innerN, zi = z - zo * innerN;
    A  += zo * sAo + zi * sAi;
    Bm += zo * sBo + zi * sBi;
    C  += zo * sCo + zi * sCi;

    __shared__ float As[2][BM * AST];
    constexpr int BSZ = TRANS_B ? (BN * BNT) : (BKT * BNN);
    __shared__ float Bs[2][BSZ];

    const int tid   = threadIdx.x;
    const int mtile = blockIdx.y * BM;
    const int ntile = blockIdx.x * BN;

    const int warp = tid >> 5, lane = tid & 31;
    const int wm = (warp & 3) * 32, wn = (warp >> 2) * 64;
    const int g = lane >> 2, l4 = lane & 3;

    auto loadA = [&](int buf, int k0) {
        #pragma unroll
        for (int i = 0; i < 2; i++) {
            int idx = tid + i * 256;
            int row = idx >> 2;
            int col = (idx & 3) * 4;
            const float* src = A + (long)(mtile + row) * lda + k0 + col;
            cp16(&As[buf][row * AST + col], src, true);
        }
    };
    auto loadB = [&](int buf, int k0) {
        if constexpr (!TRANS_B) {
            #pragma unroll
            for (int i = 0; i < 2; i++) {
                int idx = tid + i * 256;
                int r = idx >> 5;
                int c = (idx & 31) * 4;
                bool valid = (ntile + c) < N;
                const float* src = Bm + (long)(k0 + r) * ldb + ntile + c;
                cp16(&Bs[buf][r * BNN + c], src, valid);
            }
        } else {
            #pragma unroll
            for (int i = 0; i < 2; i++) {
                int idx = tid + i * 256;
                int r = idx >> 2;
                int c = (idx & 3) * 4;
                bool valid = (ntile + r) < N;
                const float* src = Bm + (long)(ntile + r) * ldb + k0 + c;
                cp16(&Bs[buf][r * BNT + c], src, valid);
            }
        }
    };

    float acc[2][8][4] = {};

    loadA(0, 0); loadB(0, 0); cp_commit();

    const int nk = K / BKT;
    for (int kt = 0; kt < nk; kt++) {
        int buf = kt & 1;
        if (kt + 1 < nk) { loadA(buf ^ 1, (kt + 1) * BKT); loadB(buf ^ 1, (kt + 1) * BKT); }
        cp_commit();
        cp_wait<1>();
        __syncthreads();

        #pragma unroll
        for (int kk = 0; kk < BKT; kk += 8) {
            uint32_t af[2][4];
            #pragma unroll
            for (int mi = 0; mi < 2; mi++) {
                const float* base = &As[buf][(wm + mi * 16 + g) * AST + kk];
                af[mi][0] = f2tf32(base[l4]);
                af[mi][1] = f2tf32(base[8 * AST + l4]);
                af[mi][2] = f2tf32(base[l4 + 4]);
                af[mi][3] = f2tf32(base[8 * AST + l4 + 4]);
            }
            #pragma unroll
            for (int ni = 0; ni < 8; ni++) {
                int n = wn + ni * 8 + g;
                uint32_t bf[2];
                if constexpr (TRANS_B) {
                    bf[0] = f2tf32(Bs[buf][n * BNT + kk + l4]);
                    bf[1] = f2tf32(Bs[buf][n * BNT + kk + l4 + 4]);
                } else {
                    bf[0] = f2tf32(Bs[buf][(kk + l4) * BNN + n]);
                    bf[1] = f2tf32(Bs[buf][(kk + l4 + 4) * BNN + n]);
                }
                #pragma unroll
                for (int mi = 0; mi < 2; mi++) mma8(acc[mi][ni], af[mi], bf);
            }
        }
        __syncthreads();
    }

    #pragma unroll
    for (int mi = 0; mi < 2; mi++) {
        #pragma unroll
        for (int ni = 0; ni < 8; ni++) {
            int c0 = ntile + wn + ni * 8 + 2 * l4;
            if (c0 >= N) continue;
            int r0 = mtile + wm + mi * 16 + g;
            float b0 = bias ? bias[c0]     : 0.0f;
            float b1 = bias ? bias[c0 + 1] : 0.0f;
            float x0 = acc[mi][ni][0] * alpha + b0;
            float x1 = acc[mi][ni][1] * alpha + b1;
            float x2 = acc[mi][ni][2] * alpha + b0;
            float x3 = acc[mi][ni][3] * alpha + b1;
            if (EPI == 1) { x0 = gelu_f(x0); x1 = gelu_f(x1); x2 = gelu_f(x2); x3 = gelu_f(x3); }
            *(float2*)&C[(long)r0 * ldc + c0]       = make_float2(x0, x1);
            *(float2*)&C[(long)(r0 + 8) * ldc + c0] = make_float2(x2, x3);
        }
    }
}

// ---------------- fused flash attention ----------------
// One block per (q-tile of 128 rows, batch*head). KV streamed in 64-row steps.
#define FBQ 128
#define FBK 64
#define QST 68     // DHEAD + 4
#define KST 68
#define PST 68     // FBK + 4

struct FlashSmem {
    float Qs[FBQ * QST];
    float Ks[FBK * KST];
    float Vs[FBK * KST];
    float Ps[FBQ * PST];
    float pm[FBQ * 2];
    float ps[FBQ * 2];
    float m_s[FBQ];
    float l_s[FBQ];
    float mb_s[FBK];
};
#define FSMEM ((int)sizeof(FlashSmem))

__global__ __launch_bounds__(256, 2)
void flash_attn(const float* __restrict__ q, const float* __restrict__ k,
                const float* __restrict__ v, const int* __restrict__ mask,
                float* __restrict__ ctx)
{
    extern __shared__ char fsm_raw[];
    FlashSmem* sm = (FlashSmem*)fsm_raw;

    const int tid = threadIdx.x;
    const int qt  = blockIdx.x;           // 0..3
    const int bh  = blockIdx.y;           // 0..383
    const int b = bh / NHEADS, hd = bh - b * NHEADS;
    const long base = (long)b * SEQ * HID + (long)hd * DHEAD;
    const float* Qg = q + base + (long)qt * FBQ * HID;
    const float* Kg = k + base;
    const float* Vg = v + base;

    const int warp = tid >> 5, lane = tid & 31;
    const int wm  = (warp & 3) * 32;
    const int wnS = (warp >> 2) * 32;     // S col half (0 / 32)
    const int wnO = (warp >> 2) * 32;     // O col half
    const int wcol = warp >> 2;
    const int g = lane >> 2, l4 = lane & 3;

    // load Q tile (128 x 64): 2048 float4 over 256 threads
    #pragma unroll
    for (int i = 0; i < 8; i++) {
        int idx = tid + i * 256;
        int r = idx >> 4;
        int c = (idx & 15) * 4;
        cp16(&sm->Qs[r * QST + c], Qg + (long)r * HID + c, true);
    }
    cp_commit();

    if (tid < FBQ) { sm->m_s[tid] = -3.4e38f; sm->l_s[tid] = 0.0f; }

    float accO[2][4][4] = {};

    for (int j = 0; j < SEQ / FBK; j++) {
        __syncthreads();   // prior-iter smem reads done (incl. init on j=0)
        // load K,V tiles (64 x 64 each): 1024 float4 each
        #pragma unroll
        for (int i = 0; i < 4; i++) {
            int idx = tid + i * 256;
            int r = idx >> 4;
            int c = (idx & 15) * 4;
            cp16(&sm->Ks[r * KST + c], Kg + (long)(j * FBK + r) * HID + c, true);
        }
        #pragma unroll
        for (int i = 0; i < 4; i++) {
            int idx = tid + i * 256;
            int r = idx >> 4;
            int c = (idx & 15) * 4;
            cp16(&sm->Vs[r * KST + c], Vg + (long)(j * FBK + r) * HID + c, true);
        }
        if (tid < FBK)
            sm->mb_s[tid] = (1.0f - (float)mask[b * SEQ + j * FBK + tid]) * (-1e9f);
        cp_commit();
        cp_wait<0>();
        __syncthreads();

        // ---- S = (Q @ K^T) * scale + bias ----
        float accS[2][4][4] = {};
        #pragma unroll
        for (int kk = 0; kk < DHEAD; kk += 8) {
            uint32_t af[2][4];
            #pragma unroll
            for (int mi = 0; mi < 2; mi++) {
                const float* bp = &sm->Qs[(wm + mi * 16 + g) * QST + kk];
                af[mi][0] = f2tf32(bp[l4]);
                af[mi][1] = f2tf32(bp[8 * QST + l4]);
                af[mi][2] = f2tf32(bp[l4 + 4]);
                af[mi][3] = f2tf32(bp[8 * QST + l4 + 4]);
            }
            #pragma unroll
            for (int ni = 0; ni < 4; ni++) {
                int n = wnS + ni * 8 + g;
                uint32_t bf[2];
                bf[0] = f2tf32(sm->Ks[n * KST + kk + l4]);
                bf[1] = f2tf32(sm->Ks[n * KST + kk + l4 + 4]);
                #pragma unroll
                for (int mi = 0; mi < 2; mi++) mma8(accS[mi][ni], af[mi], bf);
            }
        }
        #pragma unroll
        for (int mi = 0; mi < 2; mi++)
            #pragma unroll
            for (int ni = 0; ni < 4; ni++) {
                int c0 = wnS + ni * 8 + 2 * l4;
                float bb0 = sm->mb_s[c0], bb1 = sm->mb_s[c0 + 1];
                accS[mi][ni][0] = accS[mi][ni][0] * 0.125f + bb0;
                accS[mi][ni][1] = accS[mi][ni][1] * 0.125f + bb1;
                accS[mi][ni][2] = accS[mi][ni][2] * 0.125f + bb0;
                accS[mi][ni][3] = accS[mi][ni][3] * 0.125f + bb1;
            }

        // ---- online softmax ----
        float m_old[2][2];
        #pragma unroll
        for (int mi = 0; mi < 2; mi++) {
            m_old[mi][0] = sm->m_s[wm + mi * 16 + g];
            m_old[mi][1] = sm->m_s[wm + mi * 16 + g + 8];
        }
        #pragma unroll
        for (int mi = 0; mi < 2; mi++) {
            float v0 = -3.4e38f, v1 = -3.4e38f;
            #pragma unroll
            for (int ni = 0; ni < 4; ni++) {
                v0 = fmaxf(v0, fmaxf(accS[mi][ni][0], accS[mi][ni][1]));
                v1 = fmaxf(v1, fmaxf(accS[mi][ni][2], accS[mi][ni][3]));
            }
            v0 = fmaxf(v0, __shfl_xor_sync(~0u, v0, 1));
            v0 = fmaxf(v0, __shfl_xor_sync(~0u, v0, 2));
            v1 = fmaxf(v1, __shfl_xor_sync(~0u, v1, 1));
            v1 = fmaxf(v1, __shfl_xor_sync(~0u, v1, 2));
            if (l4 == 0) {
                sm->pm[(wm + mi * 16 + g) * 2 + wcol]     = v0;
                sm->pm[(wm + mi * 16 + g + 8) * 2 + wcol] = v1;
            }
        }
        __syncthreads();
        float m_new[2][2];
        #pragma unroll
        for (int mi = 0; mi < 2; mi++) {
            int r0 = wm + mi * 16 + g;
            m_new[mi][0] = fmaxf(m_old[mi][0], fmaxf(sm->pm[r0 * 2], sm->pm[r0 * 2 + 1]));
            m_new[mi][1] = fmaxf(m_old[mi][1], fmaxf(sm->pm[(r0 + 8) * 2], sm->pm[(r0 + 8) * 2 + 1]));
        }
        #pragma unroll
        for (int mi = 0; mi < 2; mi++) {
            float s0 = 0.0f, s1 = 0.0f;
            #pragma unroll
            for (int ni = 0; ni < 4; ni++) {
                accS[mi][ni][0] = __expf(accS[mi][ni][0] - m_new[mi][0]);
                accS[mi][ni][1] = __expf(accS[mi][ni][1] - m_new[mi][0]);
                accS[mi][ni][2] = __expf(accS[mi][ni][2] - m_new[mi][1]);
                accS[mi][ni][3] = __expf(accS[mi][ni][3] - m_new[mi][1]);
                s0 += accS[mi][ni][0] + accS[mi][ni][1];
                s1 += accS[mi][ni][2] + accS[mi][ni][3];
            }
            s0 += __shfl_xor_sync(~0u, s0, 1);
            s0 += __shfl_xor_sync(~0u, s0, 2);
            s1 += __shfl_xor_sync(~0u, s1, 1);
            s1 += __shfl_xor_sync(~0u, s1, 2);
            if (l4 == 0) {
                sm->ps[(wm + mi * 16 + g) * 2 + wcol]     = s0;
                sm->ps[(wm + mi * 16 + g + 8) * 2 + wcol] = s1;
            }
        }
        __syncthreads();
        if (wcol == 0 && l4 == 0) {
            #pragma unroll
            for (int mi = 0; mi < 2; mi++) {
                int r0 = wm + mi * 16 + g;
                float a0 = __expf(m_old[mi][0] - m_new[mi][0]);
                sm->l_s[r0] = sm->l_s[r0] * a0 + sm->ps[r0 * 2] + sm->ps[r0 * 2 + 1];
                sm->m_s[r0] = m_new[mi][0];
                int r1 = r0 + 8;
                float a1 = __expf(m_old[mi][1] - m_new[mi][1]);
                sm->l_s[r1] = sm->l_s[r1] * a1 + sm->ps[r1 * 2] + sm->ps[r1 * 2 + 1];
                sm->m_s[r1] = m_new[mi][1];
            }
        }
        // rescale O (same row mapping as S)
        #pragma unroll
        for (int mi = 0; mi < 2; mi++) {
            float a0 = __expf(m_old[mi][0] - m_new[mi][0]);
            float a1 = __expf(m_old[mi][1] - m_new[mi][1]);
            #pragma unroll
            for (int ni = 0; ni < 4; ni++) {
                accO[mi][ni][0] *= a0; accO[mi][ni][1] *= a0;
                accO[mi][ni][2] *= a1; accO[mi][ni][3] *= a1;
            }
        }
        // write P to smem
        #pragma unroll
        for (int mi = 0; mi < 2; mi++)
            #pragma unroll
            for (int ni = 0; ni < 4; ni++) {
                int r0 = wm + mi * 16 + g, c0 = wnS + ni * 8 + 2 * l4;
                sm->Ps[r0 * PST + c0]           = accS[mi][ni][0];
                sm->Ps[r0 * PST + c0 + 1]       = accS[mi][ni][1];
                sm->Ps[(r0 + 8) * PST + c0]     = accS[mi][ni][2];
                sm->Ps[(r0 + 8) * PST + c0 + 1] = accS[mi][ni][3];
            }
        __syncthreads();
        // ---- O += P @ V ----
        #pragma unroll
        for (int kk = 0; kk < FBK; kk += 8) {
            uint32_t af[2][4];
            #pragma unroll
            for (int mi = 0; mi < 2; mi++) {
                const float* bp = &sm->Ps[(wm + mi * 16 + g) * PST + kk];
                af[mi][0] = f2tf32(bp[l4]);
                af[mi][1] = f2tf32(bp[8 * PST + l4]);
                af[mi][2] = f2tf32(bp[l4 + 4]);
                af[mi][3] = f2tf32(bp[8 * PST + l4 + 4]);
            }
            #pragma unroll
            for (int ni = 0; ni < 4; ni++) {
                int n = wnO + ni * 8 + g;
                uint32_t bf[2];
                bf[0] = f2tf32(sm->Vs[(kk + l4) * KST + n]);
                bf[1] = f2tf32(sm->Vs[(kk + l4 + 4) * KST + n]);
                #pragma unroll
                for (int mi = 0; mi < 2; mi++) mma8(accO[mi][ni], af[mi], bf);
            }
        }
    }

    __syncthreads();
    float* Cg = ctx + base + (long)qt * FBQ * HID;
    #pragma unroll
    for (int mi = 0; mi < 2; mi++) {
        int r0 = wm + mi * 16 + g;
        float inv0 = 1.0f / sm->l_s[r0];
        float inv1 = 1.0f / sm->l_s[r0 + 8];
        #pragma unroll
        for (int ni = 0; ni < 4; ni++) {
            int c0 = wnO + ni * 8 + 2 * l4;
            *(float2*)&Cg[(long)r0 * HID + c0] =
                make_float2(accO[mi][ni][0] * inv0, accO[mi][ni][1] * inv0);
            *(float2*)&Cg[(long)(r0 + 8) * HID + c0] =
                make_float2(accO[mi][ni][2] * inv1, accO[mi][ni][3] * inv1);
        }
    }
}

// ---------------- embeddings + LN ----------------
__global__ void embed_ln(const int* __restrict__ ids,
                         const float* __restrict__ tok, const float* __restrict__ pos,
                         const float* __restrict__ typ,
                         const float* __restrict__ gam, const float* __restrict__ bet,
                         float* __restrict__ out)
{
    __shared__ float sh[8];
    int i = blockIdx.x;
    int s = i % SEQ;
    int tid = threadIdx.x;
    long id = ids[i];
    float v[3]; float ssum = 0.0f;
    #pragma unroll
    for (int j = 0; j < 3; j++) {
        int c = tid + j * 256;
        v[j] = tok[id * HID + c] + pos[(long)s * HID + c] + typ[c];
        ssum += v[j];
    }
    float mean = blk_sum<8>(ssum, sh, tid) * (1.0f / HID);
    float vs = 0.0f;
    #pragma unroll
    for (int j = 0; j < 3; j++) { float d = v[j] - mean; vs += d * d; }
    float var = blk_sum<8>(vs, sh, tid) * (1.0f / HID);
    float inv = rsqrtf(var + 1e-12f);
    #pragma unroll
    for (int j = 0; j < 3; j++) {
        int c = tid + j * 256;
        out[(long)i * HID + c] = (v[j] - mean) * inv * gam[c] + bet[c];
    }
}

// ---------------- residual + LN ----------------
__global__ void ln_fused(const float* __restrict__ res, const float* __restrict__ x,
                         const float* __restrict__ gam, const float* __restrict__ bet,
                         float* __restrict__ out)
{
    __shared__ float sh[8];
    int row = blockIdx.x;
    int tid = threadIdx.x;
    const float* rp = res + (long)row * HID;
    const float* xp = x   + (long)row * HID;
    float v[3]; float ssum = 0.0f;
    #pragma unroll
    for (int j = 0; j < 3; j++) {
        int c = tid + j * 256;
        v[j] = rp[c] + xp[c];
        ssum += v[j];
    }
    float mean = blk_sum<8>(ssum, sh, tid) * (1.0f / HID);
    float vs = 0.0f;
    #pragma unroll
    for (int j = 0; j < 3; j++) { float d = v[j] - mean; vs += d * d; }
    float var = blk_sum<8>(vs, sh, tid) * (1.0f / HID);
    float inv = rsqrtf(var + 1e-12f);
    #pragma unroll
    for (int j = 0; j < 3; j++) {
        int c = tid + j * 256;
        out[(long)row * HID + c] = (v[j] - mean) * inv * gam[c] + bet[c];
    }
}

// ---------------- span gather + classifier ----------------
__global__ void classifier_k(const float* __restrict__ h, const int* __restrict__ spans,
                             const float* __restrict__ W, const float* __restrict__ bias,
                             float* __restrict__ out)
{
    __shared__ float sh[4 * NLBL];
    int z = blockIdx.x;
    int b = z / NSPAN;
    int s0 = spans[z * 2], s1 = spans[z * 2 + 1];
    const float* h0 = h + ((long)(b * SEQ + s0)) * HID;
    const float* h1 = h + ((long)(b * SEQ + s1)) * HID;
    float acc[NLBL] = {};
    for (int j = threadIdx.x; j < 2 * HID; j += blockDim.x) {
        float xv = (j < HID) ? h0[j] : h1[j - HID];
        const float* wr = W + (long)j * NLBL;
        #pragma unroll
        for (int c = 0; c < NLBL; c++) acc[c] += xv * wr[c];
    }
    #pragma unroll
    for (int c = 0; c < NLBL; c++) {
        float v = acc[c];
        #pragma unroll
        for (int o = 16; o > 0; o >>= 1) v += __shfl_xor_sync(0xffffffffu, v, o);
        if ((threadIdx.x & 31) == 0) sh[(threadIdx.x >> 5) * NLBL + c] = v;
    }
    __syncthreads();
    if (threadIdx.x < NLBL) {
        float t = sh[threadIdx.x] + sh[NLBL + threadIdx.x]
                + sh[2 * NLBL + threadIdx.x] + sh[3 * NLBL + threadIdx.x];
        out[(long)z * NLBL + threadIdx.x] = t + bias[threadIdx.x];
    }
}

// ---------------- host ----------------
extern "C" void kernel_launch(void* const* d_in, const int* in_sizes, int n_in,
                              void* d_out, int out_size)
{
    const int*   ids   = (const int*)d_in[0];
    const int*   mask  = (const int*)d_in[1];
    const int*   spans = (const int*)d_in[2];
    const float* tok   = (const float*)d_in[3];
    const float* pos   = (const float*)d_in[4];
    const float* typ   = (const float*)d_in[5];
    const float* embg  = (const float*)d_in[6];
    const float* embb  = (const float*)d_in[7];
    const float* Wq = (const float*)d_in[8],  *bq = (const float*)d_in[9];
    const float* Wk = (const float*)d_in[10], *bk = (const float*)d_in[11];
    const float* Wv = (const float*)d_in[12], *bv = (const float*)d_in[13];
    const float* Wo = (const float*)d_in[14], *bo = (const float*)d_in[15];
    const float* l1g = (const float*)d_in[16], *l1b = (const float*)d_in[17];
    const float* W1 = (const float*)d_in[18], *b1 = (const float*)d_in[19];
    const float* W2 = (const float*)d_in[20], *b2 = (const float*)d_in[21];
    const float* l2g = (const float*)d_in[22], *l2b = (const float*)d_in[23];
    const float* clsW = (const float*)d_in[24], *clsb = (const float*)d_in[25];
    float* out = (float*)d_out;

    float *h, *h2, *q, *k, *v, *ctx, *tmp, *ff;
    cudaGetSymbolAddress((void**)&h,   g_h);
    cudaGetSymbolAddress((void**)&h2,  g_h2);
    cudaGetSymbolAddress((void**)&q,   g_q);
    cudaGetSymbolAddress((void**)&k,   g_k);
    cudaGetSymbolAddress((void**)&v,   g_v);
    cudaGetSymbolAddress((void**)&ctx, g_ctx);
    cudaGetSymbolAddress((void**)&tmp, g_tmp);
    cudaGetSymbolAddress((void**)&ff,  g_ff);

    cudaFuncSetAttribute(flash_attn, cudaFuncAttributeMaxDynamicSharedMemorySize, FSMEM);

    embed_ln<<<NTOK, 256>>>(ids, tok, pos, typ, embg, embb, h);

    const dim3 blk(256);
    const dim3 gq (HID / BN,  NTOK / BM, 1);
    const dim3 gf1(FFD / BN,  NTOK / BM, 1);
    const dim3 gattn(SEQ / FBQ, BATCH * NHEADS);

    for (int l = 0; l < NLAYER; l++) {
        const float* wq = Wq + (long)l * HID * HID;
        const float* wk = Wk + (long)l * HID * HID;
        const float* wv = Wv + (long)l * HID * HID;
        const float* wo = Wo + (long)l * HID * HID;
        const float* w1 = W1 + (long)l * HID * FFD;
        const float* w2 = W2 + (long)l * FFD * HID;

        gemm_tf32<false,0><<<gq, blk>>>(h, HID, 0, 0, wq, HID, 0, 0,
                                        q, HID, 0, 0, bq + l * HID,
                                        NTOK, HID, HID, 1, 1.0f);
        gemm_tf32<false,0><<<gq, blk>>>(h, HID, 0, 0, wk, HID, 0, 0,
                                        k, HID, 0, 0, bk + l * HID,
                                        NTOK, HID, HID, 1, 1.0f);
        gemm_tf32<false,0><<<gq, blk>>>(h, HID, 0, 0, wv, HID, 0, 0,
                                        v, HID, 0, 0, bv + l * HID,
                                        NTOK, HID, HID, 1, 1.0f);

        flash_attn<<<gattn, 256, FSMEM>>>(q, k, v, mask, ctx);

        gemm_tf32<false,0><<<gq, blk>>>(ctx, HID, 0, 0, wo, HID, 0, 0,
                                        tmp, HID, 0, 0, bo + l * HID,
                                        NTOK, HID, HID, 1, 1.0f);

        ln_fused<<<NTOK, 256>>>(h, tmp, l1g + l * HID, l1b + l * HID, h2);

        gemm_tf32<false,1><<<gf1, blk>>>(h2, HID, 0, 0, w1, FFD, 0, 0,
                                         ff, FFD, 0, 0, b1 + l * FFD,
                                         NTOK, FFD, HID, 1, 1.0f);

        gemm_tf32<false,0><<<gq, blk>>>(ff, FFD, 0, 0, w2, HID, 0, 0,
                                        tmp, HID, 0, 0, b2 + l * HID,
                                        NTOK, HID, FFD, 1, 1.0f);

        ln_fused<<<NTOK, 256>>>(h2, tmp, l2g + l * HID, l2b + l * HID, h);
    }

    classifier_k<<<BATCH * NSPAN, 128>>>(h, spans, clsW, clsb, out);
    (void)in_sizes; (void)n_in; (void)out_size;
}